// round 1
// baseline (speedup 1.0000x reference)
#include <cuda_runtime.h>
#include <cstdint>

#define NB 128
#define NV 128000
#define KTOP 20
#define NTHREADS 1024
#define CAP 4096
#define THRESH 3.0f

__device__ __forceinline__ float fast_ex2(float x) {
    float r; asm("ex2.approx.ftz.f32 %0, %1;" : "=f"(r) : "f"(x)); return r;
}
__device__ __forceinline__ float fast_lg2(float x) {
    float r; asm("lg2.approx.ftz.f32 %0, %1;" : "=f"(r) : "f"(x)); return r;
}

// Monotone pack: larger value wins; on equal value, SMALLER index wins (jax tie rule).
__device__ __forceinline__ unsigned long long packkey(float v, int idx) {
    unsigned fb = __float_as_uint(v);
    fb = (fb & 0x80000000u) ? ~fb : (fb | 0x80000000u);
    return ((unsigned long long)fb << 32) | (unsigned long long)(~(unsigned)idx);
}

// Accurate -ln(u) for u in (0,1): poly(log1p) near 1, MUFU lg2 elsewhere.
__device__ __forceinline__ float neg_log(float u) {
    float d = u - 1.0f;                       // exact for u near 1
    float p = fmaf(d, 0.2f, -0.25f);
    p = fmaf(d, p, 0.333333333f);
    p = fmaf(d, p, -0.5f);
    p = fmaf(d, p, 1.0f);
    float lp = -d * p;                        // -log1p(d), good for d in (-0.16, 0]
    float lm = -0.693147181f * fast_lg2(u);   // rel err ~1e-6 for u <= 0.84
    return (u > 0.84f) ? lp : lm;
}

__global__ __launch_bounds__(NTHREADS) void sampler_kernel(
    const float* __restrict__ logits,
    const float* __restrict__ temp,
    const float* __restrict__ u,
    float* __restrict__ out)
{
    const int b   = blockIdx.x;
    const int tid = threadIdx.x;

    __shared__ float s_val[CAP];
    __shared__ int   s_idx[CAP];
    __shared__ int   s_cnt;
    __shared__ float s_warp[NTHREADS / 32];
    __shared__ unsigned long long s_gkey;
    __shared__ unsigned long long s_win;
    __shared__ float s_lse;
    __shared__ float s_selval[KTOP];
    __shared__ int   s_selidx[KTOP];

    if (tid == 0) { s_cnt = 0; s_gkey = 0ull; }
    __syncthreads();

    const float t      = temp[b];
    const bool  greedy = (t < 1e-5f);
    const float tt     = greedy ? 1.0f : t;
    const float inv_t  = 1.0f / tt;
    const float c      = inv_t * 1.44269504088896f;   // e = 2^(logit*c) = exp(logit/t)

    const float4* __restrict__ lg4 = (const float4*)(logits + (size_t)b * NV);
    const float4* __restrict__ u4  = (const float4*)(u      + (size_t)b * NV);

    float sumexp  = 0.0f;
    float best_e  = 0.0f;       // Gumbel race: maximize e / (-ln u)
    float best_lq = 1.0f;
    int   best_gi = 0;
    float invK    = 1e30f;      // 1.01 / best_key; accepts everything initially

    const int nvec = NV / 4;    // 32000
    #pragma unroll 2
    for (int i = tid; i < nvec; i += NTHREADS) {
        float4 L = lg4[i];
        float4 U = u4[i];
        int base = 4 * i;
        #define DO_ELEM(comp, off)                                                     \
        {                                                                              \
            float lv = L.comp; float uv = U.comp;                                      \
            float e  = fast_ex2(lv * c);                                               \
            sumexp += e;                                                               \
            /* conservative filter: -ln u >= 1-u, so rejected => key < best_key */     \
            if (fmaf(e, invK, uv) > 0.999f) {                                          \
                float lq = neg_log(uv);                                                \
                if (e * best_lq > best_e * lq) {                                       \
                    best_e = e; best_lq = lq; best_gi = base + off;                    \
                    invK = 1.01f * (best_lq / best_e);                                 \
                }                                                                      \
            }                                                                          \
            if (lv > THRESH) {                                                         \
                int p = atomicAdd(&s_cnt, 1);                                          \
                if (p < CAP) { s_val[p] = lv; s_idx[p] = base + off; }                 \
            }                                                                          \
        }
        DO_ELEM(x, 0) DO_ELEM(y, 1) DO_ELEM(z, 2) DO_ELEM(w, 3)
        #undef DO_ELEM
    }

    // ---- sumexp reduction (deterministic tree) ----
    #pragma unroll
    for (int o = 16; o; o >>= 1) sumexp += __shfl_down_sync(0xFFFFFFFFu, sumexp, o);
    if ((tid & 31) == 0) s_warp[tid >> 5] = sumexp;
    __syncthreads();
    if (tid == 0) {
        float s = 0.0f;
        #pragma unroll
        for (int w = 0; w < NTHREADS / 32; w++) s += s_warp[w];
        s_lse = 0.693147181f * fast_lg2(s);   // ln(sum exp(scaled))
    }

    // ---- Gumbel winner across threads ----
    {
        float fkey = best_e / best_lq;        // >= 0, finite
        atomicMax(&s_gkey, packkey(fkey, best_gi));
    }
    __syncthreads();

    // ---- top-K selection ----
    const int cnt = s_cnt;
    const bool okc = (cnt >= KTOP) && (cnt <= CAP);
    unsigned long long bound = 0xFFFFFFFFFFFFFFFFull;

    for (int r = 0; r < KTOP; r++) {
        __syncthreads();
        if (tid == 0) s_win = 0ull;
        __syncthreads();
        unsigned long long loc = 0ull;
        if (okc) {
            for (int p = tid; p < cnt; p += NTHREADS) {
                unsigned long long k = packkey(s_val[p], s_idx[p]);
                if (k < bound && k > loc) loc = k;
            }
        } else {
            // robust fallback: full-row argmax with exclusion (rare; data-independent safety)
            const float* lrow = logits + (size_t)b * NV;
            for (int p = tid; p < NV; p += NTHREADS) {
                unsigned long long k = packkey(lrow[p], p);
                if (k < bound && k > loc) loc = k;
            }
        }
        if (loc) atomicMax(&s_win, loc);
        __syncthreads();
        unsigned long long w = s_win;
        bound = w;
        if (tid == 0) {
            unsigned fb = (unsigned)(w >> 32);
            fb = (fb & 0x80000000u) ? (fb ^ 0x80000000u) : ~fb;
            s_selval[r] = __uint_as_float(fb);
            s_selidx[r] = (int)(~(unsigned)(w & 0xFFFFFFFFull));
        }
    }
    __syncthreads();

    // ---- write outputs: [sampled(NB) | topk_logprobs(NB*K) | topk_indices(NB*K)] ----
    if (tid < KTOP) {
        float lp = s_selval[tid] * inv_t - s_lse;
        out[NB + b * KTOP + tid]             = lp;
        out[NB + NB * KTOP + b * KTOP + tid] = (float)s_selidx[tid];
    }
    if (tid == 0) {
        int gi = (int)(~(unsigned)(s_gkey & 0xFFFFFFFFull));
        int samp = greedy ? s_selidx[0] : gi;
        out[b] = (float)samp;
    }
}

extern "C" void kernel_launch(void* const* d_in, const int* in_sizes, int n_in,
                              void* d_out, int out_size) {
    const float* logits = (const float*)d_in[0];
    const float* temp   = (const float*)d_in[1];
    const float* u      = (const float*)d_in[2];
    (void)in_sizes; (void)n_in; (void)out_size;
    sampler_kernel<<<NB, NTHREADS>>>(logits, temp, u, (float*)d_out);
}

// round 2
// speedup vs baseline: 1.4698x; 1.4698x over previous
#include <cuda_runtime.h>
#include <cstdint>

#define NB 128
#define NV 128000
#define KTOP 20
#define NTHREADS 1024
#define CAP 4096
#define THRESH 3.0f

__device__ __forceinline__ float fast_ex2(float x) {
    float r; asm("ex2.approx.ftz.f32 %0, %1;" : "=f"(r) : "f"(x)); return r;
}
__device__ __forceinline__ float fast_lg2(float x) {
    float r; asm("lg2.approx.ftz.f32 %0, %1;" : "=f"(r) : "f"(x)); return r;
}

// Monotone pack: larger value wins; on equal value, SMALLER index wins (jax tie rule).
__device__ __forceinline__ unsigned long long packkey(float v, int idx) {
    unsigned fb = __float_as_uint(v);
    fb = (fb & 0x80000000u) ? ~fb : (fb | 0x80000000u);
    return ((unsigned long long)fb << 32) | (unsigned long long)(~(unsigned)idx);
}

// Accurate -ln(u) for u in (0,1): poly(log1p) near 1, MUFU lg2 elsewhere.
__device__ __forceinline__ float neg_log(float u) {
    float d = u - 1.0f;
    float p = fmaf(d, 0.2f, -0.25f);
    p = fmaf(d, p, 0.333333333f);
    p = fmaf(d, p, -0.5f);
    p = fmaf(d, p, 1.0f);
    float lp = -d * p;                        // -log1p(d), good for d in (-0.16, 0]
    float lm = -0.693147181f * fast_lg2(u);
    return (u > 0.84f) ? lp : lm;
}

__global__ __launch_bounds__(NTHREADS) void sampler_kernel(
    const float* __restrict__ logits,
    const float* __restrict__ temp,
    const float* __restrict__ u,
    float* __restrict__ out)
{
    const int b   = blockIdx.x;
    const int tid = threadIdx.x;

    __shared__ float s_val[CAP];
    __shared__ int   s_idx[CAP];
    __shared__ int   s_cnt;
    __shared__ float s_warp[NTHREADS / 32];
    __shared__ unsigned long long s_gkey;
    __shared__ unsigned long long s_win;
    __shared__ float s_lse;
    __shared__ float s_selval[KTOP];
    __shared__ int   s_selidx[KTOP];

    if (tid == 0) { s_cnt = 0; s_gkey = 0ull; }
    __syncthreads();

    const float t      = temp[b];
    const bool  greedy = (t < 1e-5f);
    const float tt     = greedy ? 1.0f : t;
    const float inv_t  = 1.0f / tt;
    const float c      = inv_t * 1.44269504088896f;

    const float4* __restrict__ lg4 = (const float4*)(logits + (size_t)b * NV);
    const float4* __restrict__ u4  = (const float4*)(u      + (size_t)b * NV);

    float acc0 = 0.0f, acc1 = 0.0f;
    float best_e  = 0.0f;
    float best_lq = 1.0f;
    int   best_gi = 0;
    float invK    = 1e30f;

    // rare path: shared append (top-k candidate) + exact log (Gumbel update)
    #define RARE(lv, uv, ee, gidx)                                                  \
    {                                                                               \
        if ((lv) > THRESH) {                                                        \
            int p = atomicAdd(&s_cnt, 1);                                           \
            if (p < CAP) { s_val[p] = (lv); s_idx[p] = (gidx); }                    \
        }                                                                           \
        if (fmaf((ee), invK, (uv)) > 0.999f) {                                      \
            float lq = neg_log(uv);                                                 \
            if ((ee) * best_lq > best_e * lq) {                                     \
                best_e = (ee); best_lq = lq; best_gi = (gidx);                      \
                invK = 1.01f * (lq / (ee));                                         \
            }                                                                       \
        }                                                                           \
    }

    const int nvec = NV / 4;   // 32000
    int i = tid;
    for (; i + NTHREADS < nvec; i += 2 * NTHREADS) {
        float4 L0 = __ldcs(lg4 + i);
        float4 L1 = __ldcs(lg4 + i + NTHREADS);
        float4 U0 = __ldcs(u4  + i);
        float4 U1 = __ldcs(u4  + i + NTHREADS);

        float e0 = fast_ex2(L0.x * c), e1 = fast_ex2(L0.y * c);
        float e2 = fast_ex2(L0.z * c), e3 = fast_ex2(L0.w * c);
        float e4 = fast_ex2(L1.x * c), e5 = fast_ex2(L1.y * c);
        float e6 = fast_ex2(L1.z * c), e7 = fast_ex2(L1.w * c);
        acc0 += (e0 + e1) + (e2 + e3);
        acc1 += (e4 + e5) + (e6 + e7);

        bool c0 = (L0.x > THRESH) || (fmaf(e0, invK, U0.x) > 0.999f);
        bool c1 = (L0.y > THRESH) || (fmaf(e1, invK, U0.y) > 0.999f);
        bool c2 = (L0.z > THRESH) || (fmaf(e2, invK, U0.z) > 0.999f);
        bool c3 = (L0.w > THRESH) || (fmaf(e3, invK, U0.w) > 0.999f);
        bool c4 = (L1.x > THRESH) || (fmaf(e4, invK, U1.x) > 0.999f);
        bool c5 = (L1.y > THRESH) || (fmaf(e5, invK, U1.y) > 0.999f);
        bool c6 = (L1.z > THRESH) || (fmaf(e6, invK, U1.z) > 0.999f);
        bool c7 = (L1.w > THRESH) || (fmaf(e7, invK, U1.w) > 0.999f);
        bool any = (c0 | c1 | c2 | c3) | (c4 | c5 | c6 | c7);

        if (__ballot_sync(0xFFFFFFFFu, any)) {
            int g0 = 4 * i, g1 = 4 * (i + NTHREADS);
            RARE(L0.x, U0.x, e0, g0 + 0) RARE(L0.y, U0.y, e1, g0 + 1)
            RARE(L0.z, U0.z, e2, g0 + 2) RARE(L0.w, U0.w, e3, g0 + 3)
            RARE(L1.x, U1.x, e4, g1 + 0) RARE(L1.y, U1.y, e5, g1 + 1)
            RARE(L1.z, U1.z, e6, g1 + 2) RARE(L1.w, U1.w, e7, g1 + 3)
        }
    }
    if (i < nvec) {   // tail (warp-uniform by construction: boundaries align to 2048)
        float4 L0 = __ldcs(lg4 + i);
        float4 U0 = __ldcs(u4  + i);
        float e0 = fast_ex2(L0.x * c), e1 = fast_ex2(L0.y * c);
        float e2 = fast_ex2(L0.z * c), e3 = fast_ex2(L0.w * c);
        acc0 += (e0 + e1) + (e2 + e3);
        bool c0 = (L0.x > THRESH) || (fmaf(e0, invK, U0.x) > 0.999f);
        bool c1 = (L0.y > THRESH) || (fmaf(e1, invK, U0.y) > 0.999f);
        bool c2 = (L0.z > THRESH) || (fmaf(e2, invK, U0.z) > 0.999f);
        bool c3 = (L0.w > THRESH) || (fmaf(e3, invK, U0.w) > 0.999f);
        if (__ballot_sync(0xFFFFFFFFu, (c0 | c1) | (c2 | c3))) {
            int g0 = 4 * i;
            RARE(L0.x, U0.x, e0, g0 + 0) RARE(L0.y, U0.y, e1, g0 + 1)
            RARE(L0.z, U0.z, e2, g0 + 2) RARE(L0.w, U0.w, e3, g0 + 3)
        }
    }
    #undef RARE

    // ---- sumexp reduction ----
    float sumexp = acc0 + acc1;
    #pragma unroll
    for (int o = 16; o; o >>= 1) sumexp += __shfl_down_sync(0xFFFFFFFFu, sumexp, o);
    if ((tid & 31) == 0) s_warp[tid >> 5] = sumexp;

    // ---- Gumbel winner across threads ----
    atomicMax(&s_gkey, packkey(best_e / best_lq, best_gi));
    __syncthreads();

    if (tid == 0) {
        float s = 0.0f;
        #pragma unroll
        for (int w = 0; w < NTHREADS / 32; w++) s += s_warp[w];
        s_lse = 0.693147181f * fast_lg2(s);
    }

    // ---- top-K: single-pass rank selection over shared candidates ----
    const int cnt = s_cnt;
    const bool okc = (cnt >= KTOP) && (cnt <= CAP);
    if (okc) {
        for (int p = tid; p < cnt; p += NTHREADS) {
            float v = s_val[p]; int ix = s_idx[p];
            unsigned long long my = packkey(v, ix);
            int rank = 0;
            for (int j = 0; j < cnt; j++)
                rank += (packkey(s_val[j], s_idx[j]) > my) ? 1 : 0;
            if (rank < KTOP) { s_selval[rank] = v; s_selidx[rank] = ix; }
        }
    } else {
        // robust fallback: 20 rounds of global argmax with exclusion (statistically never)
        unsigned long long bound = 0xFFFFFFFFFFFFFFFFull;
        const float* lrow = logits + (size_t)b * NV;
        for (int r = 0; r < KTOP; r++) {
            __syncthreads();
            if (tid == 0) s_win = 0ull;
            __syncthreads();
            unsigned long long loc = 0ull;
            for (int p = tid; p < NV; p += NTHREADS) {
                unsigned long long k = packkey(lrow[p], p);
                if (k < bound && k > loc) loc = k;
            }
            if (loc) atomicMax(&s_win, loc);
            __syncthreads();
            unsigned long long w = s_win;
            bound = w;
            if (tid == 0) {
                unsigned fb = (unsigned)(w >> 32);
                fb = (fb & 0x80000000u) ? (fb ^ 0x80000000u) : ~fb;
                s_selval[r] = __uint_as_float(fb);
                s_selidx[r] = (int)(~(unsigned)(w & 0xFFFFFFFFull));
            }
        }
    }
    __syncthreads();

    // ---- outputs: [sampled(NB) | topk_logprobs(NB*K) | topk_indices(NB*K)] ----
    if (tid < KTOP) {
        float lp = s_selval[tid] * inv_t - s_lse;
        out[NB + b * KTOP + tid]             = lp;
        out[NB + NB * KTOP + b * KTOP + tid] = (float)s_selidx[tid];
    }
    if (tid == 0) {
        int gi = (int)(~(unsigned)(s_gkey & 0xFFFFFFFFull));
        out[b] = (float)(greedy ? s_selidx[0] : gi);
    }
}

extern "C" void kernel_launch(void* const* d_in, const int* in_sizes, int n_in,
                              void* d_out, int out_size) {
    const float* logits = (const float*)d_in[0];
    const float* temp   = (const float*)d_in[1];
    const float* u      = (const float*)d_in[2];
    (void)in_sizes; (void)n_in; (void)out_size;
    sampler_kernel<<<NB, NTHREADS>>>(logits, temp, u, (float*)d_out);
}

// round 3
// speedup vs baseline: 1.5670x; 1.0661x over previous
#include <cuda_runtime.h>
#include <cstdint>

#define NB 128
#define NV 128000
#define KTOP 20
#define NTHREADS 1024
#define CAP 4096
#define THRESH 3.0f

__device__ __forceinline__ float fast_ex2(float x) {
    float r; asm("ex2.approx.ftz.f32 %0, %1;" : "=f"(r) : "f"(x)); return r;
}
__device__ __forceinline__ float fast_lg2(float x) {
    float r; asm("lg2.approx.ftz.f32 %0, %1;" : "=f"(r) : "f"(x)); return r;
}

// Monotone pack: larger value wins; on equal value, SMALLER index wins (jax tie rule).
__device__ __forceinline__ unsigned long long packkey(float v, int idx) {
    unsigned fb = __float_as_uint(v);
    fb = (fb & 0x80000000u) ? ~fb : (fb | 0x80000000u);
    return ((unsigned long long)fb << 32) | (unsigned long long)(~(unsigned)idx);
}

// Accurate -ln(u) for u in (0,1): poly(log1p) near 1, MUFU lg2 elsewhere.
__device__ __forceinline__ float neg_log(float u) {
    float d = u - 1.0f;
    float p = fmaf(d, 0.2f, -0.25f);
    p = fmaf(d, p, 0.333333333f);
    p = fmaf(d, p, -0.5f);
    p = fmaf(d, p, 1.0f);
    float lp = -d * p;                        // -log1p(d), good for d in (-0.16, 0]
    float lm = -0.693147181f * fast_lg2(u);
    return (u > 0.84f) ? lp : lm;
}

__global__ __launch_bounds__(NTHREADS) void sampler_kernel(
    const float* __restrict__ logits,
    const float* __restrict__ temp,
    const float* __restrict__ u,
    float* __restrict__ out)
{
    const int b   = blockIdx.x;
    const int tid = threadIdx.x;

    __shared__ float s_val[CAP];
    __shared__ int   s_idx[CAP];
    __shared__ int   s_cnt;
    __shared__ float s_warp[NTHREADS / 32];
    __shared__ unsigned long long s_gkey;
    __shared__ unsigned long long s_win;
    __shared__ float s_lse;
    __shared__ float s_selval[KTOP];
    __shared__ int   s_selidx[KTOP];

    if (tid == 0) { s_cnt = 0; s_gkey = 0ull; }
    __syncthreads();

    const float t      = temp[b];
    const bool  greedy = (t < 1e-5f);
    const float tt     = greedy ? 1.0f : t;
    const float inv_t  = 1.0f / tt;
    const float c      = inv_t * 1.44269504088896f;

    const float4* __restrict__ lg4 = (const float4*)(logits + (size_t)b * NV);
    const float4* __restrict__ u4  = (const float4*)(u      + (size_t)b * NV);

    float acc0 = 0.0f, acc1 = 0.0f;
    float best_e  = 0.0f;
    float best_lq = 1.0f;
    int   best_gi = 0;
    float invK    = 1e30f;

    // Per-element rare path: top-k append and/or exact Gumbel update.
    // Executed divergently; cost amortizes as body × P(any lane fires) ~ 1.8 instr/elem.
    #define RARE(lv, uv, ee, gidx)                                                  \
    {                                                                               \
        if ((lv) > THRESH) {                                                        \
            int p = atomicAdd(&s_cnt, 1);                                           \
            if (p < CAP) { s_val[p] = (lv); s_idx[p] = (gidx); }                    \
        }                                                                           \
        if (fmaf((ee), invK, (uv)) > 0.999f) {                                      \
            float lq = neg_log(uv);                                                 \
            if ((ee) * best_lq > best_e * lq) {                                     \
                best_e = (ee); best_lq = lq; best_gi = (gidx);                      \
                invK = 1.01f * (lq / (ee));                                         \
            }                                                                       \
        }                                                                           \
    }

    #define ELEM(lv, uv, ee, gidx)                                                  \
    {                                                                               \
        bool hot = ((lv) > THRESH) | (fmaf((ee), invK, (uv)) > 0.999f);             \
        if (hot) RARE(lv, uv, ee, gidx)                                             \
    }

    const int nvec = NV / 4;   // 32000
    int i = tid;
    for (; i + NTHREADS < nvec; i += 2 * NTHREADS) {
        float4 L0 = __ldcs(lg4 + i);
        float4 L1 = __ldcs(lg4 + i + NTHREADS);
        float4 U0 = __ldcs(u4  + i);
        float4 U1 = __ldcs(u4  + i + NTHREADS);

        float e0 = fast_ex2(L0.x * c), e1 = fast_ex2(L0.y * c);
        float e2 = fast_ex2(L0.z * c), e3 = fast_ex2(L0.w * c);
        float e4 = fast_ex2(L1.x * c), e5 = fast_ex2(L1.y * c);
        float e6 = fast_ex2(L1.z * c), e7 = fast_ex2(L1.w * c);
        acc0 += (e0 + e1) + (e2 + e3);
        acc1 += (e4 + e5) + (e6 + e7);

        int g0 = 4 * i, g1 = 4 * (i + NTHREADS);
        ELEM(L0.x, U0.x, e0, g0 + 0) ELEM(L0.y, U0.y, e1, g0 + 1)
        ELEM(L0.z, U0.z, e2, g0 + 2) ELEM(L0.w, U0.w, e3, g0 + 3)
        ELEM(L1.x, U1.x, e4, g1 + 0) ELEM(L1.y, U1.y, e5, g1 + 1)
        ELEM(L1.z, U1.z, e6, g1 + 2) ELEM(L1.w, U1.w, e7, g1 + 3)
    }
    if (i < nvec) {
        float4 L0 = __ldcs(lg4 + i);
        float4 U0 = __ldcs(u4  + i);
        float e0 = fast_ex2(L0.x * c), e1 = fast_ex2(L0.y * c);
        float e2 = fast_ex2(L0.z * c), e3 = fast_ex2(L0.w * c);
        acc0 += (e0 + e1) + (e2 + e3);
        int g0 = 4 * i;
        ELEM(L0.x, U0.x, e0, g0 + 0) ELEM(L0.y, U0.y, e1, g0 + 1)
        ELEM(L0.z, U0.z, e2, g0 + 2) ELEM(L0.w, U0.w, e3, g0 + 3)
    }
    #undef ELEM
    #undef RARE

    // ---- sumexp reduction ----
    float sumexp = acc0 + acc1;
    #pragma unroll
    for (int o = 16; o; o >>= 1) sumexp += __shfl_down_sync(0xFFFFFFFFu, sumexp, o);
    if ((tid & 31) == 0) s_warp[tid >> 5] = sumexp;

    // ---- Gumbel winner across threads ----
    atomicMax(&s_gkey, packkey(best_e / best_lq, best_gi));
    __syncthreads();

    if (tid == 0) {
        float s = 0.0f;
        #pragma unroll
        for (int w = 0; w < NTHREADS / 32; w++) s += s_warp[w];
        s_lse = 0.693147181f * fast_lg2(s);
    }

    // ---- top-K: single-pass rank selection over shared candidates ----
    const int cnt = s_cnt;
    const bool okc = (cnt >= KTOP) && (cnt <= CAP);
    if (okc) {
        for (int p = tid; p < cnt; p += NTHREADS) {
            float v = s_val[p]; int ix = s_idx[p];
            unsigned long long my = packkey(v, ix);
            int rank = 0;
            for (int j = 0; j < cnt; j++)
                rank += (packkey(s_val[j], s_idx[j]) > my) ? 1 : 0;
            if (rank < KTOP) { s_selval[rank] = v; s_selidx[rank] = ix; }
        }
    } else {
        // robust fallback: 20 rounds of global argmax with exclusion (statistically never)
        unsigned long long bound = 0xFFFFFFFFFFFFFFFFull;
        const float* lrow = logits + (size_t)b * NV;
        for (int r = 0; r < KTOP; r++) {
            __syncthreads();
            if (tid == 0) s_win = 0ull;
            __syncthreads();
            unsigned long long loc = 0ull;
            for (int p = tid; p < NV; p += NTHREADS) {
                unsigned long long k = packkey(lrow[p], p);
                if (k < bound && k > loc) loc = k;
            }
            if (loc) atomicMax(&s_win, loc);
            __syncthreads();
            unsigned long long w = s_win;
            bound = w;
            if (tid == 0) {
                unsigned fb = (unsigned)(w >> 32);
                fb = (fb & 0x80000000u) ? (fb ^ 0x80000000u) : ~fb;
                s_selval[r] = __uint_as_float(fb);
                s_selidx[r] = (int)(~(unsigned)(w & 0xFFFFFFFFull));
            }
        }
    }
    __syncthreads();

    // ---- outputs: [sampled(NB) | topk_logprobs(NB*K) | topk_indices(NB*K)] ----
    if (tid < KTOP) {
        float lp = s_selval[tid] * inv_t - s_lse;
        out[NB + b * KTOP + tid]             = lp;
        out[NB + NB * KTOP + b * KTOP + tid] = (float)s_selidx[tid];
    }
    if (tid == 0) {
        int gi = (int)(~(unsigned)(s_gkey & 0xFFFFFFFFull));
        out[b] = (float)(greedy ? s_selidx[0] : gi);
    }
}

extern "C" void kernel_launch(void* const* d_in, const int* in_sizes, int n_in,
                              void* d_out, int out_size) {
    const float* logits = (const float*)d_in[0];
    const float* temp   = (const float*)d_in[1];
    const float* u      = (const float*)d_in[2];
    (void)in_sizes; (void)n_in; (void)out_size;
    sampler_kernel<<<NB, NTHREADS>>>(logits, temp, u, (float*)d_out);
}